// round 15
// baseline (speedup 1.0000x reference)
#include <cuda_runtime.h>
#include <math.h>
#include <stdint.h>

#define VOCAB  32000
#define EMB    512
#define HID    1024
#define LABELS 64
#define NB     32
#define SEQ    512
#define MTOT   (NB * SEQ)   // 16384

// ---------------- scratch (device globals; no allocation allowed) -----------
__device__ float g_buf0[(size_t)NB * SEQ * HID];   // xp0 -> h0 (in-place)
__device__ float g_buf1[(size_t)NB * SEQ * HID];   // xp1 -> h1 (in-place)
// per-(group,CTA) flags, each on its OWN 128B line, single writer each
#define FLAG_STRIDE 32
__device__ unsigned g_flags0[4 * 32 * FLAG_STRIDE];
__device__ unsigned g_flags1[4 * 32 * FLAG_STRIDE];

__global__ void reset_kernel(unsigned* f0, unsigned* f1)
{
    int i = blockIdx.x * blockDim.x + threadIdx.x;
    f0[i] = 0u;
    f1[i] = 0u;
}

// ---------------- bf16 helpers ----------------------------------------------
// pack: lower 16 bits = element at smaller k (v0), upper = v1
__device__ __forceinline__ uint32_t pack_bf16x2(float v0, float v1)
{
    uint32_t r;
    asm("cvt.rn.bf16x2.f32 %0, %1, %2;" : "=r"(r) : "f"(v1), "f"(v0));
    return r;
}

// split (v0,v1) into hi bf16x2 and lo bf16x2 (lo = v - float(hi))
__device__ __forceinline__ void bsplit(float v0, float v1, uint32_t& hi, uint32_t& lo)
{
    hi = pack_bf16x2(v0, v1);
    float h0 = __uint_as_float(hi << 16);
    float h1 = __uint_as_float(hi & 0xffff0000u);
    lo = pack_bf16x2(v0 - h0, v1 - h1);
}

__device__ __forceinline__ void mma_bf16(float* d, const uint32_t* a, const uint32_t* b)
{
    asm volatile(
        "mma.sync.aligned.m16n8k16.row.col.f32.bf16.bf16.f32 "
        "{%0,%1,%2,%3},{%4,%5,%6,%7},{%8,%9},{%0,%1,%2,%3};"
        : "+f"(d[0]), "+f"(d[1]), "+f"(d[2]), "+f"(d[3])
        : "r"(a[0]), "r"(a[1]), "r"(a[2]), "r"(a[3]), "r"(b[0]), "r"(b[1]));
}

__device__ __forceinline__ void cp16(uint32_t saddr, const void* gptr)
{
    asm volatile("cp.async.cg.shared.global [%0], [%1], 16;"
                 :: "r"(saddr), "l"(gptr));
}
__device__ __forceinline__ void cp_commit()
{
    asm volatile("cp.async.commit_group;");
}

__device__ __forceinline__ float2 ldcg_f2(const float* p)
{
    float2 v;
    asm volatile("ld.global.cg.v2.f32 {%0, %1}, [%2];"
                 : "=f"(v.x), "=f"(v.y) : "l"(p));
    return v;
}

// ---------------- 3x-bf16 tensor-core GEMM (cp.async pipelined) --------------
// C[m,n] = sum_k A[m,k] * W[n,k] + bias   (A row-major [M,K], W row-major [N,K])
template<int BM, int BN, bool GATHER>
__global__ void __launch_bounds__((BM / 64) * (BN / 32) * 32, 2)
gemm_bf16(const float* __restrict__ A, const int* __restrict__ tokens,
          const float* __restrict__ W, const float* __restrict__ bias1,
          const float* __restrict__ bias2, float* __restrict__ C,
          int N, int K)
{
    constexpr int BK = 32;
    constexpr int NWX = BN / 32;
    constexpr int NW  = (BM / 64) * NWX;
    constexpr int T   = NW * 32;
    constexpr int LDA = BM * 8 / T;
    constexpr int LDB = BN * 8 / T;

    extern __shared__ float gsm[];
    float* As = gsm;                          // [2][BM][36]
    float* Bs = gsm + 2 * BM * 36;            // [2][BN][36]
    int*  toks = (int*)(Bs + 2 * BN * 36);    // [BM]

    const int tid  = threadIdx.x;
    const int lane = tid & 31;
    const int warp = tid >> 5;
    const int wy   = warp / NWX;
    const int wx   = warp % NWX;
    const int gr   = lane >> 2;
    const int gc   = lane & 3;

    const int bm = blockIdx.y * BM;
    const int bn = blockIdx.x * BN;

    if constexpr (GATHER) {
        if (tid < BM) toks[tid] = tokens[bm + tid];
        __syncthreads();
    }

    const uint32_t sA = (uint32_t)__cvta_generic_to_shared(As);
    const uint32_t sB = (uint32_t)__cvta_generic_to_shared(Bs);

    auto issue = [&](int k0, int s) {
#pragma unroll
        for (int i = 0; i < LDA; i++) {
            int idx = tid + i * T;
            int row = idx >> 3, kq = (idx & 7) * 4;
            const float* p;
            if constexpr (GATHER) p = A + (size_t)toks[row] * K;
            else                  p = A + (size_t)(bm + row) * K;
            cp16(sA + (uint32_t)((s * BM + row) * 36 + kq) * 4, p + k0 + kq);
        }
#pragma unroll
        for (int i = 0; i < LDB; i++) {
            int idx = tid + i * T;
            int row = idx >> 3, kq = (idx & 7) * 4;
            cp16(sB + (uint32_t)((s * BN + row) * 36 + kq) * 4,
                 W + (size_t)(bn + row) * K + k0 + kq);
        }
        cp_commit();
    };

    float acc[4][4][4];
#pragma unroll
    for (int i = 0; i < 4; i++)
#pragma unroll
        for (int j = 0; j < 4; j++)
#pragma unroll
            for (int r = 0; r < 4; r++) acc[i][j][r] = 0.f;

    const int iters = K / BK;
    issue(0, 0);

    for (int it = 0; it < iters; ++it) {
        if (it + 1 < iters) {
            issue((it + 1) * BK, (it + 1) & 1);
            asm volatile("cp.async.wait_group 1;");
        } else {
            asm volatile("cp.async.wait_group 0;");
        }
        __syncthreads();

        const int cur = it & 1;
        const float* Ac = As + cur * BM * 36;
        const float* Bc = Bs + cur * BN * 36;

#pragma unroll
        for (int s = 0; s < 2; ++s) {         // two k16 chunks per BK=32
            uint32_t ah[4][4], al[4][4], bh4[4][2], bl4[4][2];
#pragma unroll
            for (int i = 0; i < 4; i++) {
                int row = wy * 64 + i * 16 + gr;
                int col = s * 16 + 2 * gc;
                float2 v0 = *(const float2*)&Ac[(row    ) * 36 + col    ];
                float2 v1 = *(const float2*)&Ac[(row + 8) * 36 + col    ];
                float2 v2 = *(const float2*)&Ac[(row    ) * 36 + col + 8];
                float2 v3 = *(const float2*)&Ac[(row + 8) * 36 + col + 8];
                bsplit(v0.x, v0.y, ah[i][0], al[i][0]);
                bsplit(v1.x, v1.y, ah[i][1], al[i][1]);
                bsplit(v2.x, v2.y, ah[i][2], al[i][2]);
                bsplit(v3.x, v3.y, ah[i][3], al[i][3]);
            }
#pragma unroll
            for (int j = 0; j < 4; j++) {
                int nrow = wx * 32 + j * 8 + gr;
                int col  = s * 16 + 2 * gc;
                float2 u0 = *(const float2*)&Bc[nrow * 36 + col    ];
                float2 u1 = *(const float2*)&Bc[nrow * 36 + col + 8];
                bsplit(u0.x, u0.y, bh4[j][0], bl4[j][0]);
                bsplit(u1.x, u1.y, bh4[j][1], bl4[j][1]);
            }
#pragma unroll
            for (int i = 0; i < 4; i++)
#pragma unroll
                for (int j = 0; j < 4; j++) {
                    mma_bf16(acc[i][j], al[i], bh4[j]);
                    mma_bf16(acc[i][j], ah[i], bl4[j]);
                    mma_bf16(acc[i][j], ah[i], bh4[j]);
                }
        }
        __syncthreads();
    }

    float bsv[4][2];
#pragma unroll
    for (int j = 0; j < 4; j++) {
        int c = bn + wx * 32 + j * 8 + gc * 2;
        bsv[j][0] = bias1[c]     + (bias2 ? bias2[c]     : 0.f);
        bsv[j][1] = bias1[c + 1] + (bias2 ? bias2[c + 1] : 0.f);
    }
#pragma unroll
    for (int i = 0; i < 4; i++) {
        int r0 = bm + wy * 64 + i * 16 + gr;
#pragma unroll
        for (int j = 0; j < 4; j++) {
            int c = bn + wx * 32 + j * 8 + gc * 2;
            float2 v0 = make_float2(acc[i][j][0] + bsv[j][0], acc[i][j][1] + bsv[j][1]);
            float2 v1 = make_float2(acc[i][j][2] + bsv[j][0], acc[i][j][3] + bsv[j][1]);
            *(float2*)&C[(size_t)r0 * N + c]       = v0;
            *(float2*)&C[(size_t)(r0 + 8) * N + c] = v1;
        }
    }
}

template<int BM, int BN>
constexpr int gemm_smem() { return (2 * (BM + BN) * 36) * 4 + BM * 4; }

// ---------------- persistent bf16x2 MMA dataflow scan ------------------------
// grid: (4 batch-groups of 8, 32 row-blocks of 32) = 128 CTAs, 256 threads.
// Dataflow sync with single-writer flags (round-12 design).
// B fragments loaded DIRECTLY gmem -> registers: thread (gr,gc) of warp w
// needs exactly h[batch gr][kw + kt*16 + 2gc (+8)] -> 16x LDG.64, MLP=16.
// No smem staging hop (no STS/LDS/syncwarp on the critical path).
#define RED_LD      9                          // 8 warps + 1 pad
#define SCAN_SMEM   (256 * RED_LD * 4)

__global__ void __launch_bounds__(256, 1)
scan_mma(const float* __restrict__ Whh, float* __restrict__ buf,
         unsigned* __restrict__ flags)
{
    extern __shared__ float smem[];
    float* red = smem;                         // [256][RED_LD]

    const int tid  = threadIdx.x;
    const int lane = tid & 31;
    const int warp = tid >> 5;
    const int gr   = lane >> 2;                // 0..7
    const int gc   = lane & 3;                 // 0..3
    const int kw   = warp * 128;               // this warp's K slice

    const int batch_base = blockIdx.x * 8;     // 0,8,16,24
    const int row_base   = blockIdx.y * 32;    // 0..992

    // flag this CTA produces (own 128B line)
    unsigned* my_flag = flags + (blockIdx.x * 32 + blockIdx.y) * FLAG_STRIDE;
    // flag this lane polls: producer CTA 4*warp + (lane&3) of own group
    const unsigned* poll_flag =
        flags + (blockIdx.x * 32 + 4 * warp + (lane & 3)) * FLAG_STRIDE;

    // ---- preload W fragments (hi/lo bf16x2) into registers, once -----------
    uint32_t wh[2][8][4], wl[2][8][4];
#pragma unroll
    for (int i = 0; i < 2; i++)
#pragma unroll
        for (int kt = 0; kt < 8; kt++)
#pragma unroll
            for (int q = 0; q < 4; q++) {
                int r = row_base + i * 16 + gr + ((q & 1) ? 8 : 0);
                int k = kw + kt * 16 + 2 * gc + ((q >= 2) ? 8 : 0);
                float2 wv = *(const float2*)&Whh[(size_t)r * HID + k];
                bsplit(wv.x, wv.y, wh[i][kt][q], wl[i][kt][q]);
            }

    // ---- output mapping: b = tid>>5, r = tid&31 (coalesced 128B stores) ----
    const int ob   = tid >> 5;                 // 0..7
    const int orow = tid & 31;                 // 0..31
    const size_t my_base = (size_t)(batch_base + ob) * SEQ * HID + row_base + orow;

    // B-fragment source for this thread: batch gr of own group, k-offset in
    // own warp's K-slice
    const float* hb_base = buf + (size_t)(batch_base + gr) * SEQ * HID
                               + kw + 2 * gc;

    float xv = __ldcg(buf + my_base);          // xp for t=0

    for (int t = 0; t < SEQ; ++t) {
        // ---- wait for THIS warp's 4 producers; load B fragments directly ---
        float2 u[8][2];
        if (t > 0) {
            const unsigned tgt = (unsigned)t;
            unsigned v;
            do {
                asm volatile("ld.acquire.gpu.global.u32 %0, [%1];"
                             : "=r"(v) : "l"(poll_flag) : "memory");
            } while (__any_sync(0xffffffffu, v < tgt));

            const float* hb = hb_base + (size_t)(t - 1) * HID;
#pragma unroll
            for (int kt = 0; kt < 8; kt++) {
                u[kt][0] = ldcg_f2(hb + kt * 16);
                u[kt][1] = ldcg_f2(hb + kt * 16 + 8);
            }
        } else {
#pragma unroll
            for (int kt = 0; kt < 8; kt++) {
                u[kt][0] = make_float2(0.f, 0.f);
                u[kt][1] = make_float2(0.f, 0.f);
            }
        }

        // ---- MMA: 2 m-tiles x 8 kt x 3 passes, 2 chains ---------------------
        float acc[2][2][4];
#pragma unroll
        for (int i = 0; i < 2; i++)
#pragma unroll
            for (int c = 0; c < 2; c++)
#pragma unroll
                for (int q = 0; q < 4; q++) acc[i][c][q] = 0.f;

#pragma unroll
        for (int kt = 0; kt < 8; kt++) {
            uint32_t bh[2], bl[2];
            bsplit(u[kt][0].x, u[kt][0].y, bh[0], bl[0]);
            bsplit(u[kt][1].x, u[kt][1].y, bh[1], bl[1]);
            const int ch = kt & 1;
#pragma unroll
            for (int i = 0; i < 2; i++) {
                mma_bf16(acc[i][ch], wl[i][kt], bh);
                mma_bf16(acc[i][ch], wh[i][kt], bl);
                mma_bf16(acc[i][ch], wh[i][kt], bh);
            }
        }

        // ---- cross-warp K reduction ----------------------------------------
#pragma unroll
        for (int i = 0; i < 2; i++) {
            int r0 = i * 16 + gr;
            int b0 = 2 * gc;
            red[((b0    ) * 32 + r0    ) * RED_LD + warp] = acc[i][0][0] + acc[i][1][0];
            red[((b0 + 1) * 32 + r0    ) * RED_LD + warp] = acc[i][0][1] + acc[i][1][1];
            red[((b0    ) * 32 + r0 + 8) * RED_LD + warp] = acc[i][0][2] + acc[i][1][2];
            red[((b0 + 1) * 32 + r0 + 8) * RED_LD + warp] = acc[i][0][3] + acc[i][1][3];
        }
        __syncthreads();

        float s = 0.f;
#pragma unroll
        for (int w2 = 0; w2 < 8; w2++) s += red[tid * RED_LD + w2];

        float h = tanhf(xv + s);
        buf[my_base + (size_t)t * HID] = h;      // overwrite xp in place

        // ---- prefetch next xp (own slot; untouched until step t+1) ----------
        float xv_next = 0.f;
        if (t + 1 < SEQ)
            xv_next = __ldcg(buf + my_base + (size_t)(t + 1) * HID);

        // ---- publish: all CTA stores done -> release-store own flag ---------
        __syncthreads();   // h stores visible CTA-wide; red[] reads done (WAR)
        if (t < SEQ - 1 && tid == 0) {
            unsigned pub = (unsigned)(t + 1);
            asm volatile("st.release.gpu.global.u32 [%0], %1;"
                         :: "l"(my_flag), "r"(pub) : "memory");
        }
        xv = xv_next;
    }
}

// ---------------- host launcher ---------------------------------------------
extern "C" void kernel_launch(void* const* d_in, const int* in_sizes, int n_in,
                              void* d_out, int out_size)
{
    const int*   tokens = (const int*)  d_in[0];
    const float* emb    = (const float*)d_in[1];
    const float* W_ih0  = (const float*)d_in[2];
    const float* W_hh0  = (const float*)d_in[3];
    const float* b_ih0  = (const float*)d_in[4];
    const float* b_hh0  = (const float*)d_in[5];
    const float* W_ih1  = (const float*)d_in[6];
    const float* W_hh1  = (const float*)d_in[7];
    const float* b_ih1  = (const float*)d_in[8];
    const float* b_hh1  = (const float*)d_in[9];
    const float* W_out  = (const float*)d_in[10];
    const float* b_out  = (const float*)d_in[11];
    float* out = (float*)d_out;

    float *buf0, *buf1;
    unsigned *f0, *f1;
    cudaGetSymbolAddress((void**)&buf0, g_buf0);
    cudaGetSymbolAddress((void**)&buf1, g_buf1);
    cudaGetSymbolAddress((void**)&f0, g_flags0);
    cudaGetSymbolAddress((void**)&f1, g_flags1);

    constexpr int SM128 = gemm_smem<128, 128>();
    constexpr int SM64  = gemm_smem<128, 64>();

    cudaFuncSetAttribute(scan_mma,
        cudaFuncAttributeMaxDynamicSharedMemorySize, SCAN_SMEM);
    cudaFuncSetAttribute((const void*)gemm_bf16<128, 128, true>,
        cudaFuncAttributeMaxDynamicSharedMemorySize, SM128);
    cudaFuncSetAttribute((const void*)gemm_bf16<128, 128, false>,
        cudaFuncAttributeMaxDynamicSharedMemorySize, SM128);
    cudaFuncSetAttribute((const void*)gemm_bf16<128, 64, false>,
        cudaFuncAttributeMaxDynamicSharedMemorySize, SM64);

    dim3 gproj(HID / 128, MTOT / 128);   // (8, 128)
    dim3 gout(1, MTOT / 128);            // (1, 128)
    dim3 gscan(4, 32);                   // 128 CTAs

    reset_kernel<<<4 * 32 * FLAG_STRIDE / 256, 256>>>(f0, f1);

    // layer 0: xp0 = gather(emb, tokens) @ W_ih0^T + (b_ih0 + b_hh0)
    gemm_bf16<128, 128, true ><<<gproj, 256, SM128>>>(emb, tokens, W_ih0, b_ih0,
                                                      b_hh0, buf0, HID, EMB);
    scan_mma<<<gscan, 256, SCAN_SMEM>>>(W_hh0, buf0, f0);

    // layer 1: xp1 = h0 @ W_ih1^T + (b_ih1 + b_hh1)
    gemm_bf16<128, 128, false><<<gproj, 256, SM128>>>(buf0, nullptr, W_ih1, b_ih1,
                                                      b_hh1, buf1, HID, HID);
    scan_mma<<<gscan, 256, SCAN_SMEM>>>(W_hh1, buf1, f1);

    // output: out = h1 @ W_out^T + b_out
    gemm_bf16<128, 64, false><<<gout, 128, SM64>>>(buf1, nullptr, W_out, b_out,
                                                   nullptr, out, LABELS, HID);
}

// round 17
// speedup vs baseline: 1.0954x; 1.0954x over previous
#include <cuda_runtime.h>
#include <math.h>
#include <stdint.h>

#define VOCAB  32000
#define EMB    512
#define HID    1024
#define LABELS 64
#define NB     32
#define SEQ    512
#define MTOT   (NB * SEQ)   // 16384

// ---------------- scratch (device globals; no allocation allowed) -----------
__device__ float g_buf0[(size_t)NB * SEQ * HID];   // xp0 -> h0 (in-place)
__device__ float g_buf1[(size_t)NB * SEQ * HID];   // xp1 -> h1 (in-place)
// per-(group,CTA) flags, each on its OWN 128B line, single writer each
#define FLAG_STRIDE 32
__device__ unsigned g_flags0[4 * 32 * FLAG_STRIDE];
__device__ unsigned g_flags1[4 * 32 * FLAG_STRIDE];

__global__ void reset_kernel(unsigned* f0, unsigned* f1)
{
    int i = blockIdx.x * blockDim.x + threadIdx.x;
    f0[i] = 0u;
    f1[i] = 0u;
}

// ---------------- bf16 helpers ----------------------------------------------
// pack: lower 16 bits = element at smaller k (v0), upper = v1
__device__ __forceinline__ uint32_t pack_bf16x2(float v0, float v1)
{
    uint32_t r;
    asm("cvt.rn.bf16x2.f32 %0, %1, %2;" : "=r"(r) : "f"(v1), "f"(v0));
    return r;
}

// split (v0,v1) into hi bf16x2 and lo bf16x2 (lo = v - float(hi))
__device__ __forceinline__ void bsplit(float v0, float v1, uint32_t& hi, uint32_t& lo)
{
    hi = pack_bf16x2(v0, v1);
    float h0 = __uint_as_float(hi << 16);
    float h1 = __uint_as_float(hi & 0xffff0000u);
    lo = pack_bf16x2(v0 - h0, v1 - h1);
}

__device__ __forceinline__ void mma_bf16(float* d, const uint32_t* a, const uint32_t* b)
{
    asm volatile(
        "mma.sync.aligned.m16n8k16.row.col.f32.bf16.bf16.f32 "
        "{%0,%1,%2,%3},{%4,%5,%6,%7},{%8,%9},{%0,%1,%2,%3};"
        : "+f"(d[0]), "+f"(d[1]), "+f"(d[2]), "+f"(d[3])
        : "r"(a[0]), "r"(a[1]), "r"(a[2]), "r"(a[3]), "r"(b[0]), "r"(b[1]));
}

__device__ __forceinline__ void cp16(uint32_t saddr, const void* gptr)
{
    asm volatile("cp.async.cg.shared.global [%0], [%1], 16;"
                 :: "r"(saddr), "l"(gptr));
}
__device__ __forceinline__ void cp_commit()
{
    asm volatile("cp.async.commit_group;");
}

// ---------------- 3x-bf16 tensor-core GEMM (cp.async, 1 sync/iter) ----------
// C[m,n] = sum_k A[m,k] * W[n,k] + bias   (A row-major [M,K], W row-major [N,K])
// Mainloop: wait(0); sync; issue(it+1) [other buffer, safe: all warps are past
// reading it-1 which used that buffer]; compute(it). Single barrier per iter,
// prefetch still overlaps compute.
template<int BM, int BN, bool GATHER>
__global__ void __launch_bounds__((BM / 64) * (BN / 32) * 32, 2)
gemm_bf16(const float* __restrict__ A, const int* __restrict__ tokens,
          const float* __restrict__ W, const float* __restrict__ bias1,
          const float* __restrict__ bias2, float* __restrict__ C,
          int N, int K)
{
    constexpr int BK = 32;
    constexpr int NWX = BN / 32;
    constexpr int NW  = (BM / 64) * NWX;
    constexpr int T   = NW * 32;
    constexpr int LDA = BM * 8 / T;
    constexpr int LDB = BN * 8 / T;

    extern __shared__ float gsm[];
    float* As = gsm;                          // [2][BM][36]
    float* Bs = gsm + 2 * BM * 36;            // [2][BN][36]
    int*  toks = (int*)(Bs + 2 * BN * 36);    // [BM]

    const int tid  = threadIdx.x;
    const int lane = tid & 31;
    const int warp = tid >> 5;
    const int wy   = warp / NWX;
    const int wx   = warp % NWX;
    const int gr   = lane >> 2;
    const int gc   = lane & 3;

    const int bm = blockIdx.y * BM;
    const int bn = blockIdx.x * BN;

    if constexpr (GATHER) {
        if (tid < BM) toks[tid] = tokens[bm + tid];
        __syncthreads();
    }

    const uint32_t sA = (uint32_t)__cvta_generic_to_shared(As);
    const uint32_t sB = (uint32_t)__cvta_generic_to_shared(Bs);

    auto issue = [&](int k0, int s) {
#pragma unroll
        for (int i = 0; i < LDA; i++) {
            int idx = tid + i * T;
            int row = idx >> 3, kq = (idx & 7) * 4;
            const float* p;
            if constexpr (GATHER) p = A + (size_t)toks[row] * K;
            else                  p = A + (size_t)(bm + row) * K;
            cp16(sA + (uint32_t)((s * BM + row) * 36 + kq) * 4, p + k0 + kq);
        }
#pragma unroll
        for (int i = 0; i < LDB; i++) {
            int idx = tid + i * T;
            int row = idx >> 3, kq = (idx & 7) * 4;
            cp16(sB + (uint32_t)((s * BN + row) * 36 + kq) * 4,
                 W + (size_t)(bn + row) * K + k0 + kq);
        }
        cp_commit();
    };

    float acc[4][4][4];
#pragma unroll
    for (int i = 0; i < 4; i++)
#pragma unroll
        for (int j = 0; j < 4; j++)
#pragma unroll
            for (int r = 0; r < 4; r++) acc[i][j][r] = 0.f;

    const int iters = K / BK;
    issue(0, 0);

    for (int it = 0; it < iters; ++it) {
        asm volatile("cp.async.wait_group 0;");
        __syncthreads();

        if (it + 1 < iters)
            issue((it + 1) * BK, (it + 1) & 1);   // other buffer; overlaps compute

        const int cur = it & 1;
        const float* Ac = As + cur * BM * 36;
        const float* Bc = Bs + cur * BN * 36;

#pragma unroll
        for (int s = 0; s < 2; ++s) {         // two k16 chunks per BK=32
            uint32_t ah[4][4], al[4][4], bh4[4][2], bl4[4][2];
#pragma unroll
            for (int i = 0; i < 4; i++) {
                int row = wy * 64 + i * 16 + gr;
                int col = s * 16 + 2 * gc;
                float2 v0 = *(const float2*)&Ac[(row    ) * 36 + col    ];
                float2 v1 = *(const float2*)&Ac[(row + 8) * 36 + col    ];
                float2 v2 = *(const float2*)&Ac[(row    ) * 36 + col + 8];
                float2 v3 = *(const float2*)&Ac[(row + 8) * 36 + col + 8];
                bsplit(v0.x, v0.y, ah[i][0], al[i][0]);
                bsplit(v1.x, v1.y, ah[i][1], al[i][1]);
                bsplit(v2.x, v2.y, ah[i][2], al[i][2]);
                bsplit(v3.x, v3.y, ah[i][3], al[i][3]);
            }
#pragma unroll
            for (int j = 0; j < 4; j++) {
                int nrow = wx * 32 + j * 8 + gr;
                int col  = s * 16 + 2 * gc;
                float2 u0 = *(const float2*)&Bc[nrow * 36 + col    ];
                float2 u1 = *(const float2*)&Bc[nrow * 36 + col + 8];
                bsplit(u0.x, u0.y, bh4[j][0], bl4[j][0]);
                bsplit(u1.x, u1.y, bh4[j][1], bl4[j][1]);
            }
#pragma unroll
            for (int i = 0; i < 4; i++)
#pragma unroll
                for (int j = 0; j < 4; j++) {
                    mma_bf16(acc[i][j], al[i], bh4[j]);
                    mma_bf16(acc[i][j], ah[i], bl4[j]);
                    mma_bf16(acc[i][j], ah[i], bh4[j]);
                }
        }
    }

    float bsv[4][2];
#pragma unroll
    for (int j = 0; j < 4; j++) {
        int c = bn + wx * 32 + j * 8 + gc * 2;
        bsv[j][0] = bias1[c]     + (bias2 ? bias2[c]     : 0.f);
        bsv[j][1] = bias1[c + 1] + (bias2 ? bias2[c + 1] : 0.f);
    }
#pragma unroll
    for (int i = 0; i < 4; i++) {
        int r0 = bm + wy * 64 + i * 16 + gr;
#pragma unroll
        for (int j = 0; j < 4; j++) {
            int c = bn + wx * 32 + j * 8 + gc * 2;
            float2 v0 = make_float2(acc[i][j][0] + bsv[j][0], acc[i][j][1] + bsv[j][1]);
            float2 v1 = make_float2(acc[i][j][2] + bsv[j][0], acc[i][j][3] + bsv[j][1]);
            *(float2*)&C[(size_t)r0 * N + c]       = v0;
            *(float2*)&C[(size_t)(r0 + 8) * N + c] = v1;
        }
    }
}

template<int BM, int BN>
constexpr int gemm_smem() { return (2 * (BM + BN) * 36) * 4 + BM * 4; }

// ---------------- persistent bf16x2 MMA dataflow scan ------------------------
// (byte-identical to round 12 — the 2732us champion)
// grid: (4 batch-groups of 8, 32 row-blocks of 32) = 128 CTAs, 256 threads.
// Single-writer flags; warp polls its 4 producers with one instruction.
#define HS_LD       1032                       // 1024 + 8 pad
#define RED_LD      9                          // 8 warps + 1 pad
#define SCAN_SMEM   ((8 * HS_LD + 256 * RED_LD) * 4)

__global__ void __launch_bounds__(256, 1)
scan_mma(const float* __restrict__ Whh, float* __restrict__ buf,
         unsigned* __restrict__ flags)
{
    extern __shared__ float smem[];
    float* hs  = smem;                         // [8][HS_LD]
    float* red = smem + 8 * HS_LD;             // [256][RED_LD]

    const int tid  = threadIdx.x;
    const int lane = tid & 31;
    const int warp = tid >> 5;
    const int gr   = lane >> 2;                // 0..7
    const int gc   = lane & 3;                 // 0..3
    const int kw   = warp * 128;               // this warp's K slice

    const int batch_base = blockIdx.x * 8;     // 0,8,16,24
    const int row_base   = blockIdx.y * 32;    // 0..992

    // flag this CTA produces (own 128B line)
    unsigned* my_flag = flags + (blockIdx.x * 32 + blockIdx.y) * FLAG_STRIDE;
    // flag this lane polls: producer CTA 4*warp + (lane&3) of own group
    const unsigned* poll_flag =
        flags + (blockIdx.x * 32 + 4 * warp + (lane & 3)) * FLAG_STRIDE;

    // ---- preload W fragments (hi/lo bf16x2) into registers, once -----------
    uint32_t wh[2][8][4], wl[2][8][4];
#pragma unroll
    for (int i = 0; i < 2; i++)
#pragma unroll
        for (int kt = 0; kt < 8; kt++)
#pragma unroll
            for (int q = 0; q < 4; q++) {
                int r = row_base + i * 16 + gr + ((q & 1) ? 8 : 0);
                int k = kw + kt * 16 + 2 * gc + ((q >= 2) ? 8 : 0);
                float2 wv = *(const float2*)&Whh[(size_t)r * HID + k];
                bsplit(wv.x, wv.y, wh[i][kt][q], wl[i][kt][q]);
            }

    // ---- output mapping: b = tid>>5, r = tid&31 (coalesced 128B stores) ----
    const int ob   = tid >> 5;                 // 0..7
    const int orow = tid & 31;                 // 0..31
    const size_t my_base = (size_t)(batch_base + ob) * SEQ * HID + row_base + orow;

    // zero hs (h_{-1} = 0)
    {
        float4 z = make_float4(0.f, 0.f, 0.f, 0.f);
        for (int i = tid; i < 8 * HS_LD / 4; i += 256) ((float4*)hs)[i] = z;
    }
    __syncthreads();

    const float* gbase = buf + (size_t)batch_base * SEQ * HID;

    float xv = __ldcg(buf + my_base);          // xp for t=0

    for (int t = 0; t < SEQ; ++t) {
        // ---- wait for THIS warp's 4 producers, then stage own K-slice ------
        if (t > 0) {
            const unsigned tgt = (unsigned)t;
            unsigned v;
            do {
                asm volatile("ld.acquire.gpu.global.u32 %0, [%1];"
                             : "=r"(v) : "l"(poll_flag) : "memory");
            } while (__any_sync(0xffffffffu, v < tgt));

            const float* src = gbase + (size_t)(t - 1) * HID + kw;
#pragma unroll
            for (int b = 0; b < 8; b++) {
                float4 w4 = __ldcg((const float4*)(src + (size_t)b * SEQ * HID + lane * 4));
                *(float4*)&hs[b * HS_LD + kw + lane * 4] = w4;
            }
            __syncwarp();
        }

        // ---- MMA: 2 m-tiles x 8 kt x 3 passes, 2 chains ---------------------
        float acc[2][2][4];
#pragma unroll
        for (int i = 0; i < 2; i++)
#pragma unroll
            for (int c = 0; c < 2; c++)
#pragma unroll
                for (int q = 0; q < 4; q++) acc[i][c][q] = 0.f;

#pragma unroll
        for (int kt = 0; kt < 8; kt++) {
            const float* hp = hs + gr * HS_LD + kw + kt * 16 + 2 * gc;
            float2 u0 = *(const float2*)(hp);
            float2 u1 = *(const float2*)(hp + 8);
            uint32_t bh[2], bl[2];
            bsplit(u0.x, u0.y, bh[0], bl[0]);
            bsplit(u1.x, u1.y, bh[1], bl[1]);
            const int ch = kt & 1;
#pragma unroll
            for (int i = 0; i < 2; i++) {
                mma_bf16(acc[i][ch], wl[i][kt], bh);
                mma_bf16(acc[i][ch], wh[i][kt], bl);
                mma_bf16(acc[i][ch], wh[i][kt], bh);
            }
        }

        // ---- cross-warp K reduction ----------------------------------------
#pragma unroll
        for (int i = 0; i < 2; i++) {
            int r0 = i * 16 + gr;
            int b0 = 2 * gc;
            red[((b0    ) * 32 + r0    ) * RED_LD + warp] = acc[i][0][0] + acc[i][1][0];
            red[((b0 + 1) * 32 + r0    ) * RED_LD + warp] = acc[i][0][1] + acc[i][1][1];
            red[((b0    ) * 32 + r0 + 8) * RED_LD + warp] = acc[i][0][2] + acc[i][1][2];
            red[((b0 + 1) * 32 + r0 + 8) * RED_LD + warp] = acc[i][0][3] + acc[i][1][3];
        }
        __syncthreads();

        float s = 0.f;
#pragma unroll
        for (int w2 = 0; w2 < 8; w2++) s += red[tid * RED_LD + w2];

        float h = tanhf(xv + s);
        buf[my_base + (size_t)t * HID] = h;      // overwrite xp in place

        // ---- prefetch next xp (own slot; untouched until step t+1) ----------
        float xv_next = 0.f;
        if (t + 1 < SEQ)
            xv_next = __ldcg(buf + my_base + (size_t)(t + 1) * HID);

        // ---- publish: all CTA stores done -> release-store own flag ---------
        __syncthreads();   // h stores visible CTA-wide; red[] reads done (WAR)
        if (t < SEQ - 1 && tid == 0) {
            unsigned pub = (unsigned)(t + 1);
            asm volatile("st.release.gpu.global.u32 [%0], %1;"
                         :: "l"(my_flag), "r"(pub) : "memory");
        }
        xv = xv_next;
    }
}

// ---------------- host launcher ---------------------------------------------
extern "C" void kernel_launch(void* const* d_in, const int* in_sizes, int n_in,
                              void* d_out, int out_size)
{
    const int*   tokens = (const int*)  d_in[0];
    const float* emb    = (const float*)d_in[1];
    const float* W_ih0  = (const float*)d_in[2];
    const float* W_hh0  = (const float*)d_in[3];
    const float* b_ih0  = (const float*)d_in[4];
    const float* b_hh0  = (const float*)d_in[5];
    const float* W_ih1  = (const float*)d_in[6];
    const float* W_hh1  = (const float*)d_in[7];
    const float* b_ih1  = (const float*)d_in[8];
    const float* b_hh1  = (const float*)d_in[9];
    const float* W_out  = (const float*)d_in[10];
    const float* b_out  = (const float*)d_in[11];
    float* out = (float*)d_out;

    float *buf0, *buf1;
    unsigned *f0, *f1;
    cudaGetSymbolAddress((void**)&buf0, g_buf0);
    cudaGetSymbolAddress((void**)&buf1, g_buf1);
    cudaGetSymbolAddress((void**)&f0, g_flags0);
    cudaGetSymbolAddress((void**)&f1, g_flags1);

    constexpr int SM128 = gemm_smem<128, 128>();
    constexpr int SM64  = gemm_smem<128, 64>();

    cudaFuncSetAttribute(scan_mma,
        cudaFuncAttributeMaxDynamicSharedMemorySize, SCAN_SMEM);
    cudaFuncSetAttribute((const void*)gemm_bf16<128, 128, true>,
        cudaFuncAttributeMaxDynamicSharedMemorySize, SM128);
    cudaFuncSetAttribute((const void*)gemm_bf16<128, 128, false>,
        cudaFuncAttributeMaxDynamicSharedMemorySize, SM128);
    cudaFuncSetAttribute((const void*)gemm_bf16<128, 64, false>,
        cudaFuncAttributeMaxDynamicSharedMemorySize, SM64);

    dim3 gproj(HID / 128, MTOT / 128);   // (8, 128)
    dim3 gout(1, MTOT / 128);            // (1, 128)
    dim3 gscan(4, 32);                   // 128 CTAs

    reset_kernel<<<4 * 32 * FLAG_STRIDE / 256, 256>>>(f0, f1);

    // layer 0: xp0 = gather(emb, tokens) @ W_ih0^T + (b_ih0 + b_hh0)
    gemm_bf16<128, 128, true ><<<gproj, 256, SM128>>>(emb, tokens, W_ih0, b_ih0,
                                                      b_hh0, buf0, HID, EMB);
    scan_mma<<<gscan, 256, SCAN_SMEM>>>(W_hh0, buf0, f0);

    // layer 1: xp1 = h0 @ W_ih1^T + (b_ih1 + b_hh1)
    gemm_bf16<128, 128, false><<<gproj, 256, SM128>>>(buf0, nullptr, W_ih1, b_ih1,
                                                      b_hh1, buf1, HID, HID);
    scan_mma<<<gscan, 256, SCAN_SMEM>>>(W_hh1, buf1, f1);

    // output: out = h1 @ W_out^T + b_out
    gemm_bf16<128, 64, false><<<gout, 128, SM64>>>(buf1, nullptr, W_out, b_out,
                                                   nullptr, out, LABELS, HID);
}